// round 6
// baseline (speedup 1.0000x reference)
#include <cuda_runtime.h>
#include <math.h>

#define NG   4
#define NB   6
#define NF   8
#define NFRR 256
#define NACT 5
#define BTOT 32768

// Precomputed factorization of relation similarity:
// sim[g,n,m]*16 = feat_n^T M_g feat_m + vt_g.feat_n + vp_g.feat_m + c_g
__device__ float g_M[NG][NF * NF];
__device__ float g_vt[NG][NF];
__device__ float g_vp[NG][NF];
__device__ float g_c[NG];

__global__ void precompute_kernel(const float* __restrict__ Wt,
                                  const float* __restrict__ bt,
                                  const float* __restrict__ Wp,
                                  const float* __restrict__ bp)
{
    int g   = blockIdx.x;
    int tid = threadIdx.x;                 // 256 threads
    const float* wt  = Wt + g * NFRR * NF;
    const float* wp  = Wp + g * NFRR * NF;
    const float* btg = bt + g * NFRR;
    const float* bpg = bp + g * NFRR;
    __shared__ float red[256];

    int ef = tid & 63, q = tid >> 6;
    int e  = ef >> 3,  f = ef & 7;
    float acc = 0.f;
#pragma unroll 8
    for (int r = q * 64; r < q * 64 + 64; r++)
        acc = fmaf(wt[r * NF + e], wp[r * NF + f], acc);
    red[tid] = acc;
    __syncthreads();
    if (q == 0)
        g_M[g][ef] = (red[ef] + red[64 + ef]) + (red[128 + ef] + red[192 + ef]);
    __syncthreads();

    float a2 = 0.f;
    if (tid < 64) {
        int ff = tid & 7, s = tid >> 3;
#pragma unroll 8
        for (int r = s * 32; r < s * 32 + 32; r++)
            a2 = fmaf(wt[r * NF + ff], bpg[r], a2);
        red[tid] = a2;
    } else if (tid < 128) {
        int id = tid - 64, ff = id & 7, s = id >> 3;
#pragma unroll 8
        for (int r = s * 32; r < s * 32 + 32; r++)
            a2 = fmaf(btg[r], wp[r * NF + ff], a2);
        red[tid] = a2;
    } else if (tid < 160) {
        int s = tid - 128;
#pragma unroll
        for (int r = s * 8; r < s * 8 + 8; r++)
            a2 = fmaf(btg[r], bpg[r], a2);
        red[tid] = a2;
    }
    __syncthreads();
    if (tid < 8) {
        float sm = 0.f;
        for (int s = 0; s < 8; s++) sm += red[s * 8 + tid];
        g_vt[g][tid] = sm;
    } else if (tid < 16) {
        int ff = tid - 8;
        float sm = 0.f;
        for (int s = 0; s < 8; s++) sm += red[64 + s * 8 + ff];
        g_vp[g][ff] = sm;
    } else if (tid == 16) {
        float sm = 0.f;
        for (int k = 0; k < 32; k++) sm += red[128 + k];
        g_c[g] = sm;
    }
}

// dual-accumulator 8-dot
#define DOT8_DUAL(res, xv, wr, init)                                     \
    do {                                                                 \
        float _a0 = fmaf((xv)[0], (wr)[0], (init));                      \
        float _a1 = (xv)[1] * (wr)[1];                                   \
        _a0 = fmaf((xv)[2], (wr)[2], _a0);                               \
        _a1 = fmaf((xv)[3], (wr)[3], _a1);                               \
        _a0 = fmaf((xv)[4], (wr)[4], _a0);                               \
        _a1 = fmaf((xv)[5], (wr)[5], _a1);                               \
        _a0 = fmaf((xv)[6], (wr)[6], _a0);                               \
        _a1 = fmaf((xv)[7], (wr)[7], _a1);                               \
        (res) = _a0 + _a1;                                               \
    } while (0)

#define LOAD8(dst, src)                                                  \
    do {                                                                 \
        float4 _v0 = ((const float4*)(src))[0];                          \
        float4 _v1 = ((const float4*)(src))[1];                          \
        (dst)[0] = _v0.x; (dst)[1] = _v0.y; (dst)[2] = _v0.z;            \
        (dst)[3] = _v0.w; (dst)[4] = _v1.x; (dst)[5] = _v1.y;            \
        (dst)[6] = _v1.z; (dst)[7] = _v1.w;                              \
    } while (0)

#define STORE8(dst, src)                                                 \
    do {                                                                 \
        ((float4*)(dst))[0] = make_float4((src)[0], (src)[1], (src)[2], (src)[3]); \
        ((float4*)(dst))[1] = make_float4((src)[4], (src)[5], (src)[6], (src)[7]); \
    } while (0)

#define FSTRIDE 52   // 52 mod 32 = 20 -> the 8 groups' 4-bank footprints tile all 32 banks

// 4 threads per batch: sub = (nhalf<<1)|ghalf.  ghalf owns graphs {2g,2g+1},
// nhalf owns rows {0..2}/{3..5}.  feat[6][8] lives in SMEM per 4-lane group;
// each thread keeps only its own 3 rows in registers.
__global__ __launch_bounds__(128, 4) void gcn_main6(
    const float* __restrict__ X,     // [B,6,8]
    const float* __restrict__ P,     // [B,6,2]
    const float* __restrict__ Wext,  // [8,8]
    const float* __restrict__ bext,  // [8]
    const float* __restrict__ Wgcn,  // [4,8,8]
    const float* __restrict__ Wact,  // [5,8]
    const float* __restrict__ bact,  // [5]
    float* __restrict__ out)         // [B,5]
{
    __shared__ __align__(16) float sWext[64];
    __shared__ __align__(16) float sM[NG][64];
    __shared__ __align__(16) float sWgcn[NG][64];
    __shared__ __align__(16) float svt[NG][NF];
    __shared__ __align__(16) float svp[NG][NF];
    __shared__ __align__(16) float sWact[40];
    __shared__ float sbext[NF], sbact[NACT], sc[NG];
    __shared__ __align__(16) float sFeat[32 * FSTRIDE];   // 32 groups per block

    int tid = threadIdx.x;
    if (tid < 64) sWext[tid] = Wext[tid];
    else if (tid < 104) sWact[tid - 64] = Wact[tid - 64];
    else if (tid < 112) sbext[tid - 104] = bext[tid - 104];
    else if (tid < 117) sbact[tid - 112] = bact[tid - 112];
    else if (tid < 121) sc[tid - 117] = g_c[tid - 117];
    for (int i = tid; i < 256; i += 128) {
        ((float*)sM)[i]    = ((const float*)g_M)[i];
        ((float*)sWgcn)[i] = Wgcn[i];
    }
    if (tid < 32) {
        ((float*)svt)[tid] = ((const float*)g_vt)[tid];
        ((float*)svp)[tid] = ((const float*)g_vp)[tid];
    }

    int t     = blockIdx.x * 128 + tid;
    int b     = t >> 2;
    int sub   = t & 3;
    int ghalf = sub & 1;
    int nhalf = sub >> 1;
    int n0    = nhalf * 3;
    float* F  = &sFeat[(tid >> 2) * FSTRIDE];

    // ---- pairwise distance mask for own 3 rows (exact R1 op sequence) ----
    unsigned rowm[3];
    {
        const float4* P4 = (const float4*)(P + b * 12);
        float4 p0 = P4[0], p1 = P4[1], p2 = P4[2];
        float px[NB] = {p0.x, p0.z, p1.x, p1.z, p2.x, p2.z};
        float py[NB] = {p0.y, p0.w, p1.y, p1.w, p2.y, p2.w};
        float rr[NB];
#pragma unroll
        for (int n = 0; n < NB; n++)
            rr[n] = __fmaf_rn(py[n], py[n], __fmul_rn(px[n], px[n]));
#pragma unroll
        for (int i = 0; i < 3; i++) {
            int n = n0 + i;
            unsigned rm = 0;
#pragma unroll
            for (int m = 0; m < NB; m++) {
                float dot = __fmaf_rn(py[n], py[m], __fmul_rn(px[n], px[m]));
                float d2  = __fadd_rn(__fsub_rn(rr[n], __fmul_rn(2.0f, dot)), rr[m]);
                if (__fsqrt_rn(d2) > 4.0f) rm |= 1u << m;
            }
            rowm[i] = rm;
        }
    }

    __syncthreads();   // weights staged

    // ---- feature extension for OWN 3 rows only ----
    const float4* X4 = (const float4*)(X + b * 48);
    float featr[3][NF];
#pragma unroll
    for (int i = 0; i < 3; i++) {
        int n = n0 + i;
        float xa[NF];
        LOAD8(xa, &X4[n * 2]);
#pragma unroll
        for (int f = 0; f < NF; f++) {
            float wr[NF];
            LOAD8(wr, &sWext[f * 8]);
            float r0;
            DOT8_DUAL(r0, xa, wr, sbext[f]);
            featr[i][f] = fmaxf(r0, 0.0f);
        }
    }
    // ghalf==0 lane publishes its rows to the group's smem tile
    if (ghalf == 0) {
#pragma unroll
        for (int i = 0; i < 3; i++)
            STORE8(&F[(n0 + i) * 8], featr[i]);
    }
    __syncwarp(0xffffffffu);   // groups are warp-internal

    // ---- sphi[gg][m] = vp_g . feat_m for both of this lane's graphs ----
    float sphi[2][NB];
    {
        float vpr0[NF], vpr1[NF];
        LOAD8(vpr0, svp[ghalf * 2]);
        LOAD8(vpr1, svp[ghalf * 2 + 1]);
#pragma unroll
        for (int m = 0; m < NB; m++) {
            float fm[NF];
            LOAD8(fm, &F[m * 8]);
            DOT8_DUAL(sphi[0][m], fm, vpr0, 0.0f);
            DOT8_DUAL(sphi[1][m], fm, vpr1, 0.0f);
        }
    }

    float pl[NF];
#pragma unroll
    for (int f = 0; f < NF; f++) pl[f] = -3.402823466e38f;

#pragma unroll
    for (int i = 0; i < 3; i++) {
        int n = n0 + i;
        float gsr[NF];
#pragma unroll
        for (int f = 0; f < NF; f++) gsr[f] = 0.f;

#pragma unroll
        for (int gg = 0; gg < 2; gg++) {
            int g = ghalf * 2 + gg;

            // tt[f] = sum_e featr[i][e] * M[e][f]
            float tt[NF];
#pragma unroll
            for (int f = 0; f < NF; f++) tt[f] = 0.f;
#pragma unroll
            for (int e = 0; e < NF; e++) {
                float mr[NF];
                LOAD8(mr, &sM[g][e * 8]);
                float fv = featr[i][e];
#pragma unroll
                for (int f = 0; f < NF; f++) tt[f] = fmaf(fv, mr[f], tt[f]);
            }
            float st;
            {
                float vtr[NF];
                LOAD8(vtr, svt[g]);
                DOT8_DUAL(st, featr[i], vtr, sc[g]);
            }

            float s[NB];
#pragma unroll
            for (int m = 0; m < NB; m++) {
                float fm[NF];
                LOAD8(fm, &F[m * 8]);
                float a;
                DOT8_DUAL(a, tt, fm, st + sphi[gg][m]);
                s[m] = a * 0.0625f;   // / sqrt(256)
            }

            unsigned rm = rowm[i];
            float mx = -3.402823466e38f;
#pragma unroll
            for (int m = 0; m < NB; m++)
                if (!((rm >> m) & 1u)) mx = fmaxf(mx, s[m]);
            float w[NB];
            float ps = 0.f;
#pragma unroll
            for (int m = 0; m < NB; m++) {
                float e_ = ((rm >> m) & 1u) ? 0.0f : __expf(s[m] - mx);
                w[m] = e_; ps += e_;
            }
            float inv = 1.0f / ps;

            float agg[NF];
#pragma unroll
            for (int f = 0; f < NF; f++) agg[f] = 0.f;
#pragma unroll
            for (int m = 0; m < NB; m++) {
                float fm[NF];
                LOAD8(fm, &F[m * 8]);
                float wv = w[m] * inv;
#pragma unroll
                for (int f = 0; f < NF; f++)
                    agg[f] = fmaf(wv, fm[f], agg[f]);
            }

#pragma unroll
            for (int o = 0; o < NF; o++) {
                float wr[NF];
                LOAD8(wr, &sWgcn[g][o * 8]);
                float a;
                DOT8_DUAL(a, agg, wr, 0.0f);
                gsr[o] += fmaxf(a, 0.0f);
            }
        }

        // sum over the ghalf partner (lane xor 1), then residual + pool
#pragma unroll
        for (int f = 0; f < NF; f++)
            gsr[f] += __shfl_xor_sync(0xffffffffu, gsr[f], 1);

        float xv[NF];
        LOAD8(xv, &X4[n * 2]);
#pragma unroll
        for (int f = 0; f < NF; f++)
            pl[f] = fmaxf(pl[f], fmaf(gsr[f], 0.25f, xv[f]));
    }

    // ---- combine the two n-halves (lane xor 2) ----
#pragma unroll
    for (int f = 0; f < NF; f++) {
        float o = __shfl_xor_sync(0xffffffffu, pl[f], 2);
        pl[f] = fmaxf(pl[f], o);
    }

    // ---- activity head (lane sub==0 writes) ----
    if (sub == 0) {
        float* ob = out + b * NACT;
#pragma unroll
        for (int a = 0; a < NACT; a++) {
            float wr[NF];
            LOAD8(wr, &sWact[a * 8]);
            float acc;
            DOT8_DUAL(acc, pl, wr, sbact[a]);
            ob[a] = acc;
        }
    }
}

extern "C" void kernel_launch(void* const* d_in, const int* in_sizes, int n_in,
                              void* d_out, int out_size)
{
    const float* X    = (const float*)d_in[0];
    const float* P    = (const float*)d_in[1];
    const float* Wext = (const float*)d_in[2];
    const float* bext = (const float*)d_in[3];
    const float* Wt   = (const float*)d_in[4];
    const float* bt   = (const float*)d_in[5];
    const float* Wp   = (const float*)d_in[6];
    const float* bp   = (const float*)d_in[7];
    const float* Wgcn = (const float*)d_in[8];
    const float* Wact = (const float*)d_in[9];
    const float* bact = (const float*)d_in[10];

    precompute_kernel<<<NG, 256>>>(Wt, bt, Wp, bp);
    gcn_main6<<<BTOT * 4 / 128, 128>>>(X, P, Wext, bext, Wgcn, Wact, bact,
                                       (float*)d_out);
}

// round 8
// speedup vs baseline: 2.8220x; 2.8220x over previous
#include <cuda_runtime.h>
#include <math.h>

#define NG   4
#define NB   6
#define NF   8
#define NFRR 256
#define NACT 5
#define BTOT 32768

// Precomputed factorization of relation similarity:
// sim[g,n,m]*16 = feat_n^T M_g feat_m + vt_g.feat_n + vp_g.feat_m + c_g
__device__ float g_M[NG][NF * NF];
__device__ float g_vt[NG][NF];
__device__ float g_vp[NG][NF];
__device__ float g_c[NG];

__global__ void precompute_kernel(const float* __restrict__ Wt,
                                  const float* __restrict__ bt,
                                  const float* __restrict__ Wp,
                                  const float* __restrict__ bp)
{
    int g   = blockIdx.x;
    int tid = threadIdx.x;                 // 256 threads
    const float* wt  = Wt + g * NFRR * NF;
    const float* wp  = Wp + g * NFRR * NF;
    const float* btg = bt + g * NFRR;
    const float* bpg = bp + g * NFRR;
    __shared__ float red[256];

    int ef = tid & 63, q = tid >> 6;
    int e  = ef >> 3,  f = ef & 7;
    float acc = 0.f;
#pragma unroll 8
    for (int r = q * 64; r < q * 64 + 64; r++)
        acc = fmaf(wt[r * NF + e], wp[r * NF + f], acc);
    red[tid] = acc;
    __syncthreads();
    if (q == 0)
        g_M[g][ef] = (red[ef] + red[64 + ef]) + (red[128 + ef] + red[192 + ef]);
    __syncthreads();

    float a2 = 0.f;
    if (tid < 64) {
        int ff = tid & 7, s = tid >> 3;
#pragma unroll 8
        for (int r = s * 32; r < s * 32 + 32; r++)
            a2 = fmaf(wt[r * NF + ff], bpg[r], a2);
        red[tid] = a2;
    } else if (tid < 128) {
        int id = tid - 64, ff = id & 7, s = id >> 3;
#pragma unroll 8
        for (int r = s * 32; r < s * 32 + 32; r++)
            a2 = fmaf(btg[r], wp[r * NF + ff], a2);
        red[tid] = a2;
    } else if (tid < 160) {
        int s = tid - 128;
#pragma unroll
        for (int r = s * 8; r < s * 8 + 8; r++)
            a2 = fmaf(btg[r], bpg[r], a2);
        red[tid] = a2;
    }
    __syncthreads();
    if (tid < 8) {
        float sm = 0.f;
        for (int s = 0; s < 8; s++) sm += red[s * 8 + tid];
        g_vt[g][tid] = sm;
    } else if (tid < 16) {
        int ff = tid - 8;
        float sm = 0.f;
        for (int s = 0; s < 8; s++) sm += red[64 + s * 8 + ff];
        g_vp[g][ff] = sm;
    } else if (tid == 16) {
        float sm = 0.f;
        for (int k = 0; k < 32; k++) sm += red[128 + k];
        g_c[g] = sm;
    }
}

// dual-accumulator 8-dot
#define DOT8_DUAL(res, xv, wr, init)                                     \
    do {                                                                 \
        float _a0 = fmaf((xv)[0], (wr)[0], (init));                      \
        float _a1 = (xv)[1] * (wr)[1];                                   \
        _a0 = fmaf((xv)[2], (wr)[2], _a0);                               \
        _a1 = fmaf((xv)[3], (wr)[3], _a1);                               \
        _a0 = fmaf((xv)[4], (wr)[4], _a0);                               \
        _a1 = fmaf((xv)[5], (wr)[5], _a1);                               \
        _a0 = fmaf((xv)[6], (wr)[6], _a0);                               \
        _a1 = fmaf((xv)[7], (wr)[7], _a1);                               \
        (res) = _a0 + _a1;                                               \
    } while (0)

#define LOAD8(dst, src)                                                  \
    do {                                                                 \
        float4 _v0 = ((const float4*)(src))[0];                          \
        float4 _v1 = ((const float4*)(src))[1];                          \
        (dst)[0] = _v0.x; (dst)[1] = _v0.y; (dst)[2] = _v0.z;            \
        (dst)[3] = _v0.w; (dst)[4] = _v1.x; (dst)[5] = _v1.y;            \
        (dst)[6] = _v1.z; (dst)[7] = _v1.w;                              \
    } while (0)

#define STORE8(dst, src)                                                 \
    do {                                                                 \
        ((float4*)(dst))[0] = make_float4((src)[0], (src)[1], (src)[2], (src)[3]); \
        ((float4*)(dst))[1] = make_float4((src)[4], (src)[5], (src)[6], (src)[7]); \
    } while (0)

#define FSTR 52   // batch stride (floats) for feat/states: 16B-aligned, 8-period banks
#define SSTR 26   // batch stride for sphi

// One thread per (batch, box-row): 192 threads = 32 batches per block.
// feat + sphi + states shared per block; each thread owns one softmax row
// across all 4 graphs.  Warp 0 finishes max-pool + activity head.
__global__ __launch_bounds__(192, 3) void gcn_rows(
    const float* __restrict__ X,     // [B,6,8]
    const float* __restrict__ P,     // [B,6,2]
    const float* __restrict__ Wext,  // [8,8]
    const float* __restrict__ bext,  // [8]
    const float* __restrict__ Wgcn,  // [4,8,8]
    const float* __restrict__ Wact,  // [5,8]
    const float* __restrict__ bact,  // [5]
    float* __restrict__ out)         // [B,5]
{
    __shared__ __align__(16) float sWext[64];
    __shared__ __align__(16) float sM[NG][64];
    __shared__ __align__(16) float sWgcn[NG][64];
    __shared__ __align__(16) float svt[NG][NF];
    __shared__ __align__(16) float svp[NG][NF];
    __shared__ __align__(16) float sWact[40];
    __shared__ float sbext[NF], sbact[NACT], sc[NG];
    __shared__ __align__(16) float sFeat[32 * FSTR];
    __shared__ __align__(16) float sStates[32 * FSTR];
    __shared__ float sSphi[32 * SSTR];

    int tid = threadIdx.x;
    if (tid < 64) sWext[tid] = Wext[tid];
    else if (tid < 104) sWact[tid - 64] = Wact[tid - 64];
    else if (tid < 112) sbext[tid - 104] = bext[tid - 104];
    else if (tid < 117) sbact[tid - 112] = bact[tid - 112];
    else if (tid < 121) sc[tid - 117] = g_c[tid - 117];
    else if (tid < 153) ((float*)svt)[tid - 121] = ((const float*)g_vt)[tid - 121];
    else if (tid < 185) ((float*)svp)[tid - 153] = ((const float*)g_vp)[tid - 153];
    for (int i = tid; i < 256; i += 192) {
        ((float*)sM)[i]    = ((const float*)g_M)[i];
        ((float*)sWgcn)[i] = Wgcn[i];
    }

    int bl = tid / 6;                  // batch-local 0..31
    int n  = tid - bl * 6;             // own box row 0..5
    int b  = blockIdx.x * 32 + bl;

    // ---- distance mask, own row only (exact R1 op sequence) ----
    unsigned rowm = 0;
    {
        const float4* P4 = (const float4*)(P + b * 12);
        float4 p0 = P4[0], p1 = P4[1], p2 = P4[2];
        float px[NB] = {p0.x, p0.z, p1.x, p1.z, p2.x, p2.z};
        float py[NB] = {p0.y, p0.w, p1.y, p1.w, p2.y, p2.w};
        float rr[NB];
#pragma unroll
        for (int m = 0; m < NB; m++)
            rr[m] = __fmaf_rn(py[m], py[m], __fmul_rn(px[m], px[m]));
#pragma unroll
        for (int m = 0; m < NB; m++) {
            float dot = __fmaf_rn(py[n], py[m], __fmul_rn(px[n], px[m]));
            float d2  = __fadd_rn(__fsub_rn(rr[n], __fmul_rn(2.0f, dot)), rr[m]);
            if (__fsqrt_rn(d2) > 4.0f) rowm |= 1u << m;
        }
    }

    __syncthreads();   // weights staged

    // ---- own feat row ----
    float featr[NF];
    {
        float xr[NF];
        LOAD8(xr, X + (b * NB + n) * NF);
#pragma unroll
        for (int f = 0; f < NF; f++) {
            float wr[NF];
            LOAD8(wr, &sWext[f * 8]);
            float a;
            DOT8_DUAL(a, xr, wr, sbext[f]);
            featr[f] = fmaxf(a, 0.0f);
        }
    }
    STORE8(&sFeat[bl * FSTR + n * 8], featr);

    // ---- own sphi column: sphi[g][n] = vp_g . feat_n ----
#pragma unroll
    for (int g = 0; g < NG; g++) {
        float vpr[NF];
        LOAD8(vpr, svp[g]);
        float a;
        DOT8_DUAL(a, featr, vpr, 0.0f);
        sSphi[bl * SSTR + g * 6 + n] = a;
    }
    __syncthreads();   // feat + sphi published

    const float* Fb = &sFeat[bl * FSTR];
    const float* Sb = &sSphi[bl * SSTR];

    float gsum[NF];
#pragma unroll
    for (int f = 0; f < NF; f++) gsum[f] = 0.f;

#pragma unroll
    for (int g = 0; g < NG; g++) {
        // tt[f] = sum_e featr[e] * M[e][f]
        float tt[NF];
#pragma unroll
        for (int f = 0; f < NF; f++) tt[f] = 0.f;
#pragma unroll
        for (int e = 0; e < NF; e++) {
            float mr[NF];
            LOAD8(mr, &sM[g][e * 8]);
            float fv = featr[e];
#pragma unroll
            for (int f = 0; f < NF; f++) tt[f] = fmaf(fv, mr[f], tt[f]);
        }
        float st;
        {
            float vtr[NF];
            LOAD8(vtr, svt[g]);
            DOT8_DUAL(st, featr, vtr, sc[g]);
        }

        float s[NB];
#pragma unroll
        for (int m = 0; m < NB; m++) {
            float fm[NF];
            LOAD8(fm, &Fb[m * 8]);
            float a;
            DOT8_DUAL(a, tt, fm, st + Sb[g * 6 + m]);
            s[m] = a * 0.0625f;       // / sqrt(256)
        }

        float mx = -3.402823466e38f;
#pragma unroll
        for (int m = 0; m < NB; m++)
            if (!((rowm >> m) & 1u)) mx = fmaxf(mx, s[m]);
        float w[NB];
        float ps = 0.f;
#pragma unroll
        for (int m = 0; m < NB; m++) {
            float e_ = ((rowm >> m) & 1u) ? 0.0f : __expf(s[m] - mx);
            w[m] = e_; ps += e_;
        }
        float inv = 1.0f / ps;

        float agg[NF];
#pragma unroll
        for (int f = 0; f < NF; f++) agg[f] = 0.f;
#pragma unroll
        for (int m = 0; m < NB; m++) {
            float fm[NF];
            LOAD8(fm, &Fb[m * 8]);
            float wv = w[m] * inv;
#pragma unroll
            for (int f = 0; f < NF; f++)
                agg[f] = fmaf(wv, fm[f], agg[f]);
        }

#pragma unroll
        for (int o = 0; o < NF; o++) {
            float wr[NF];
            LOAD8(wr, &sWgcn[g][o * 8]);
            float a;
            DOT8_DUAL(a, agg, wr, 0.0f);
            gsum[o] += fmaxf(a, 0.0f);
        }
    }

    // ---- own state row: residual + mean over NG ----
    {
        float xr[NF];
        LOAD8(xr, X + (b * NB + n) * NF);
        float stt[NF];
#pragma unroll
        for (int f = 0; f < NF; f++)
            stt[f] = fmaf(gsum[f], 0.25f, xr[f]);
        STORE8(&sStates[bl * FSTR + n * 8], stt);
    }
    __syncthreads();

    // ---- max-pool + activity head: warp 0, one thread per batch ----
    if (tid < 32) {
        const float* Stb = &sStates[tid * FSTR];
        float pl[NF];
        LOAD8(pl, &Stb[0]);
#pragma unroll
        for (int m = 1; m < NB; m++) {
            float sv[NF];
            LOAD8(sv, &Stb[m * 8]);
#pragma unroll
            for (int f = 0; f < NF; f++) pl[f] = fmaxf(pl[f], sv[f]);
        }
        float* ob = out + (blockIdx.x * 32 + tid) * NACT;
#pragma unroll
        for (int a = 0; a < NACT; a++) {
            float wr[NF];
            LOAD8(wr, &sWact[a * 8]);
            float acc;
            DOT8_DUAL(acc, pl, wr, sbact[a]);
            ob[a] = acc;
        }
    }
}

extern "C" void kernel_launch(void* const* d_in, const int* in_sizes, int n_in,
                              void* d_out, int out_size)
{
    const float* X    = (const float*)d_in[0];
    const float* P    = (const float*)d_in[1];
    const float* Wext = (const float*)d_in[2];
    const float* bext = (const float*)d_in[3];
    const float* Wt   = (const float*)d_in[4];
    const float* bt   = (const float*)d_in[5];
    const float* Wp   = (const float*)d_in[6];
    const float* bp   = (const float*)d_in[7];
    const float* Wgcn = (const float*)d_in[8];
    const float* Wact = (const float*)d_in[9];
    const float* bact = (const float*)d_in[10];

    precompute_kernel<<<NG, 256>>>(Wt, bt, Wp, bp);
    gcn_rows<<<BTOT / 32, 192>>>(X, P, Wext, bext, Wgcn, Wact, bact,
                                 (float*)d_out);
}